// round 11
// baseline (speedup 1.0000x reference)
#include <cuda_runtime.h>
#include <cuda_bf16.h>
#include <cstdint>

// Problem constants
#define TT 2048
#define EE 1024
#define DD 1024
#define HH 16
#define HDIM 64
#define BB 2
#define MM (BB * TT)   // 4096
#define GK 1024        // K of both GEMMs

// ---------------------------------------------------------------------------
// Scratch
// ---------------------------------------------------------------------------
__device__ __nv_bfloat16 g_qkvh[(size_t)MM * 3 * DD];
__device__ __nv_bfloat16 g_qkvl[(size_t)MM * 3 * DD];
__device__ __nv_bfloat16 g_wah[(size_t)3 * DD * EE];
__device__ __nv_bfloat16 g_wal[(size_t)3 * DD * EE];
__device__ __nv_bfloat16 g_wph[(size_t)EE * DD];
__device__ __nv_bfloat16 g_wpl[(size_t)EE * DD];
__device__ __nv_bfloat16 g_yh[(size_t)MM * DD];
__device__ __nv_bfloat16 g_yl[(size_t)MM * DD];

// ---------------------------------------------------------------------------
// PTX helpers (base-target only)
// ---------------------------------------------------------------------------
__device__ __forceinline__ uint32_t smem_u32(const void* p) {
    uint32_t a;
    asm("{ .reg .u64 t; cvta.to.shared.u64 t, %1; cvt.u32.u64 %0, t; }"
        : "=r"(a) : "l"(p));
    return a;
}

#define LDSM_X4(R, addr) \
    asm volatile("ldmatrix.sync.aligned.m8n8.x4.shared.b16 {%0,%1,%2,%3}, [%4];" \
        : "=r"((R)[0]), "=r"((R)[1]), "=r"((R)[2]), "=r"((R)[3]) : "r"(addr))

#define LDSM_X4_T(R, addr) \
    asm volatile("ldmatrix.sync.aligned.m8n8.x4.trans.shared.b16 {%0,%1,%2,%3}, [%4];" \
        : "=r"((R)[0]), "=r"((R)[1]), "=r"((R)[2]), "=r"((R)[3]) : "r"(addr))

#define MMA_BF16(D, A, B) \
    asm volatile("mma.sync.aligned.m16n8k16.row.col.f32.bf16.bf16.f32 " \
        "{%0,%1,%2,%3},{%4,%5,%6,%7},{%8,%9},{%0,%1,%2,%3};" \
        : "+f"((D)[0]), "+f"((D)[1]), "+f"((D)[2]), "+f"((D)[3]) \
        : "r"((A)[0]), "r"((A)[1]), "r"((A)[2]), "r"((A)[3]), \
          "r"((B)[0]), "r"((B)[1]))

__device__ __forceinline__ void split_bf16(float v, __nv_bfloat16& h, __nv_bfloat16& l) {
    h = __float2bfloat16(v);
    l = __float2bfloat16(v - __bfloat162float(h));
}
__device__ __forceinline__ uint32_t pack2(__nv_bfloat16 a, __nv_bfloat16 b) {
    __nv_bfloat162 t(a, b);
    return *(uint32_t*)&t;
}
// Convert 8 fp32 -> uint4 of 8 hi-bf16 and uint4 of 8 lo-bf16.
__device__ __forceinline__ void cvt8(float4 a, float4 b, uint4& h, uint4& l) {
    float f[8] = {a.x, a.y, a.z, a.w, b.x, b.y, b.z, b.w};
    uint32_t* hp = (uint32_t*)&h;
    uint32_t* lp = (uint32_t*)&l;
    #pragma unroll
    for (int j = 0; j < 4; j++) {
        __nv_bfloat16 h0, l0, h1, l1;
        split_bf16(f[2 * j], h0, l0);
        split_bf16(f[2 * j + 1], h1, l1);
        hp[j] = pack2(h0, h1);
        lp[j] = pack2(l0, l1);
    }
}

// ---------------------------------------------------------------------------
// W [K,N] fp32 -> T [N,K] bf16 hi/lo
// ---------------------------------------------------------------------------
__global__ void transpose_split_kernel(const float* __restrict__ W,
                                       __nv_bfloat16* __restrict__ Th,
                                       __nv_bfloat16* __restrict__ Tl,
                                       int K, int N)
{
    __shared__ float tile[32][33];
    int kb = blockIdx.y * 32, nb = blockIdx.x * 32;
    int x = threadIdx.x, y0 = threadIdx.y;
    #pragma unroll
    for (int dy = 0; dy < 32; dy += 8)
        tile[y0 + dy][x] = W[(size_t)(kb + y0 + dy) * N + nb + x];
    __syncthreads();
    #pragma unroll
    for (int dy = 0; dy < 32; dy += 8) {
        float v = tile[x][y0 + dy];
        __nv_bfloat16 h, l;
        split_bf16(v, h, l);
        size_t o = (size_t)(nb + y0 + dy) * K + kb + x;
        Th[o] = h;
        Tl[o] = l;
    }
}

// ---------------------------------------------------------------------------
// mma.sync split-bf16 GEMM (R7/R10 proven config).
// If Afp != null, A is fp32 and is split to hi/lo in the loader (fused split).
// mode 0: fp32 C + bias; mode 1: bf16 hi/lo outputs.
// ---------------------------------------------------------------------------
#define GS 40

__global__ __launch_bounds__(256) void gemm_mma_kernel(
    const float* __restrict__ Afp,
    const __nv_bfloat16* __restrict__ Ah, const __nv_bfloat16* __restrict__ Al,
    const __nv_bfloat16* __restrict__ Bh, const __nv_bfloat16* __restrict__ Bl,
    const float* __restrict__ bias, float* __restrict__ C,
    __nv_bfloat16* __restrict__ Ch, __nv_bfloat16* __restrict__ Cl,
    int M, int N, int K, int mode)
{
    __shared__ __nv_bfloat16 sA[2][128][GS];
    __shared__ __nv_bfloat16 sB[2][128][GS];

    const int tid = threadIdx.x;
    const int lane = tid & 31;
    const int wid = tid >> 5;
    const int wm = wid & 3;
    const int wn = wid >> 2;
    const int m0 = blockIdx.y * 128;
    const int n0 = blockIdx.x * 128;

    const int lrow = tid >> 1;
    const int lseg = (tid & 1) * 16;

    float acc[2][8][4];
    #pragma unroll
    for (int i = 0; i < 2; i++)
        #pragma unroll
        for (int j = 0; j < 8; j++)
            #pragma unroll
            for (int r = 0; r < 4; r++) acc[i][j][r] = 0.f;

    const uint32_t sA0 = smem_u32(&sA[0][0][0]);
    const uint32_t sA1 = smem_u32(&sA[1][0][0]);
    const uint32_t sB0 = smem_u32(&sB[0][0][0]);
    const uint32_t sB1 = smem_u32(&sB[1][0][0]);

    const size_t rowA = (size_t)(m0 + lrow) * K + lseg;
    const size_t rowB = (size_t)(n0 + lrow) * K + lseg;

    uint4 pre[8];
    auto loadA = [&](size_t ka) {
        if (Afp) {
            const float* fp = Afp + ka;
            float4 a0 = *(const float4*)(fp);
            float4 a1 = *(const float4*)(fp + 4);
            float4 a2 = *(const float4*)(fp + 8);
            float4 a3 = *(const float4*)(fp + 12);
            cvt8(a0, a1, pre[0], pre[2]);
            cvt8(a2, a3, pre[1], pre[3]);
        } else {
            pre[0] = *(const uint4*)&Ah[ka];
            pre[1] = *(const uint4*)&Ah[ka + 8];
            pre[2] = *(const uint4*)&Al[ka];
            pre[3] = *(const uint4*)&Al[ka + 8];
        }
    };

    loadA(rowA);
    pre[4] = *(const uint4*)&Bh[rowB];
    pre[5] = *(const uint4*)&Bh[rowB + 8];
    pre[6] = *(const uint4*)&Bl[rowB];
    pre[7] = *(const uint4*)&Bl[rowB + 8];

    const int NC = K >> 5;
    for (int ch = 0; ch < NC; ch++) {
        *(uint4*)&sA[0][lrow][lseg]     = pre[0];
        *(uint4*)&sA[0][lrow][lseg + 8] = pre[1];
        *(uint4*)&sA[1][lrow][lseg]     = pre[2];
        *(uint4*)&sA[1][lrow][lseg + 8] = pre[3];
        *(uint4*)&sB[0][lrow][lseg]     = pre[4];
        *(uint4*)&sB[0][lrow][lseg + 8] = pre[5];
        *(uint4*)&sB[1][lrow][lseg]     = pre[6];
        *(uint4*)&sB[1][lrow][lseg + 8] = pre[7];
        __syncthreads();

        if (ch + 1 < NC) {
            int k0 = (ch + 1) * 32;
            loadA(rowA + k0);
            size_t rb = rowB + k0;
            pre[4] = *(const uint4*)&Bh[rb];
            pre[5] = *(const uint4*)&Bh[rb + 8];
            pre[6] = *(const uint4*)&Bl[rb];
            pre[7] = *(const uint4*)&Bl[rb + 8];
        }

        #pragma unroll
        for (int ks = 0; ks < 2; ks++) {
            uint32_t aA[2][2][4];
            {
                int r = lane & 15, kh = lane >> 4;
                #pragma unroll
                for (int mt = 0; mt < 2; mt++) {
                    uint32_t off =
                        (uint32_t)((wm * 32 + mt * 16 + r) * GS + ks * 16 + kh * 8) * 2;
                    LDSM_X4(aA[0][mt], sA0 + off);
                    LDSM_X4(aA[1][mt], sA1 + off);
                }
            }
            uint32_t bB[2][8][2];
            {
                int nr = ((lane >> 4) << 3) + (lane & 7);
                int kc = ks * 16 + (((lane >> 3) & 1) << 3);
                #pragma unroll
                for (int p = 0; p < 4; p++) {
                    uint32_t off =
                        (uint32_t)((wn * 64 + p * 16 + nr) * GS + kc) * 2;
                    uint32_t t[4];
                    LDSM_X4(t, sB0 + off);
                    bB[0][2 * p][0] = t[0]; bB[0][2 * p][1] = t[1];
                    bB[0][2 * p + 1][0] = t[2]; bB[0][2 * p + 1][1] = t[3];
                    LDSM_X4(t, sB1 + off);
                    bB[1][2 * p][0] = t[0]; bB[1][2 * p][1] = t[1];
                    bB[1][2 * p + 1][0] = t[2]; bB[1][2 * p + 1][1] = t[3];
                }
            }
            #pragma unroll
            for (int mt = 0; mt < 2; mt++)
                #pragma unroll
                for (int nt = 0; nt < 8; nt++) {
                    MMA_BF16(acc[mt][nt], aA[0][mt], bB[0][nt]);
                    MMA_BF16(acc[mt][nt], aA[0][mt], bB[1][nt]);
                    MMA_BF16(acc[mt][nt], aA[1][mt], bB[0][nt]);
                }
        }
        __syncthreads();
    }

    // Epilogue
    #pragma unroll
    for (int mt = 0; mt < 2; mt++) {
        int m = m0 + wm * 32 + mt * 16 + (lane >> 2);
        #pragma unroll
        for (int nt = 0; nt < 8; nt++) {
            int n = n0 + wn * 64 + nt * 8 + ((lane & 3) << 1);
            float b0 = bias[n], b1 = bias[n + 1];
            float v0 = acc[mt][nt][0] + b0, v1 = acc[mt][nt][1] + b1;
            float v2 = acc[mt][nt][2] + b0, v3 = acc[mt][nt][3] + b1;
            if (mode == 0) {
                *(float2*)&C[(size_t)m * N + n] = make_float2(v0, v1);
                *(float2*)&C[(size_t)(m + 8) * N + n] = make_float2(v2, v3);
            } else {
                __nv_bfloat16 h0, l0, h1, l1, h2, l2, h3, l3;
                split_bf16(v0, h0, l0); split_bf16(v1, h1, l1);
                split_bf16(v2, h2, l2); split_bf16(v3, h3, l3);
                *(uint32_t*)&Ch[(size_t)m * N + n] = pack2(h0, h1);
                *(uint32_t*)&Cl[(size_t)m * N + n] = pack2(l0, l1);
                *(uint32_t*)&Ch[(size_t)(m + 8) * N + n] = pack2(h2, h3);
                *(uint32_t*)&Cl[(size_t)(m + 8) * N + n] = pack2(l2, l3);
            }
        }
    }
}

// ---------------------------------------------------------------------------
// Tensor-core flash attention. V now stored row-major (like K) and read as
// B-fragments via ldmatrix.trans — the transpose scatter is gone.
// ---------------------------------------------------------------------------
#define VS 72
#define OFF_QH 0
#define OFF_QL (128 * VS)
#define OFF_KH (2 * 128 * VS)
#define OFF_KL (3 * 128 * VS)
#define OFF_VH (4 * 128 * VS)
#define OFF_VL (5 * 128 * VS)
#define ATTN_SMEM (6 * 128 * VS * 2)   // 110592 B

__global__ __launch_bounds__(256) void flash_attn_mma_kernel(
    const __nv_bfloat16* __restrict__ qh, const __nv_bfloat16* __restrict__ ql,
    __nv_bfloat16* __restrict__ yh, __nv_bfloat16* __restrict__ yl)
{
    extern __shared__ __nv_bfloat16 sm[];

    const int qt = 15 - blockIdx.x;
    const int bh = blockIdx.y;
    const int b = bh >> 4, h = bh & 15;
    const int tid = threadIdx.x;
    const int lane = tid & 31;
    const int wid = tid >> 5;
    const int q0 = qt * 128;
    const size_t base = ((size_t)b * TT) * 3072 + (size_t)h * 64;

    const uint32_t sQh = smem_u32(sm + OFF_QH);
    const uint32_t sQl = smem_u32(sm + OFF_QL);
    const uint32_t sKh = smem_u32(sm + OFF_KH);
    const uint32_t sKl = smem_u32(sm + OFF_KL);
    const uint32_t sVh = smem_u32(sm + OFF_VH);
    const uint32_t sVl = smem_u32(sm + OFF_VL);

    #pragma unroll
    for (int it = 0; it < 4; it++) {
        int idx = tid + 256 * it;
        int r = idx >> 3, c8 = (idx & 7) * 8;
        size_t g = base + (size_t)(q0 + r) * 3072 + c8;
        *(uint4*)&sm[OFF_QH + r * VS + c8] = *(const uint4*)&qh[g];
        *(uint4*)&sm[OFF_QL + r * VS + c8] = *(const uint4*)&ql[g];
    }
    __syncthreads();

    uint32_t qA[2][4][4];
    {
        int r = lane & 15, kh = lane >> 4;
        #pragma unroll
        for (int ks = 0; ks < 4; ks++) {
            uint32_t off = (uint32_t)((wid * 16 + r) * VS + ks * 16 + kh * 8) * 2;
            LDSM_X4(qA[0][ks], sQh + off);
            LDSM_X4(qA[1][ks], sQl + off);
        }
    }

    float mS[2] = {-1e30f, -1e30f};
    float lS[2] = {0.f, 0.f};
    float oAcc[8][4];
    #pragma unroll
    for (int j = 0; j < 8; j++)
        #pragma unroll
        for (int r = 0; r < 4; r++) oAcc[j][r] = 0.f;

    const int nr = ((lane >> 4) << 3) + (lane & 7);
    const int kc8 = ((lane >> 3) & 1) << 3;
    const int vr = lane & 15;              // trans-ldmatrix row
    const int vc = (lane >> 4) << 3;       // trans-ldmatrix col-half

    for (int kt = 0; kt <= qt; kt++) {
        __syncthreads();
        // K and V tiles: straight row-major copies (bf16 hi/lo).
        #pragma unroll
        for (int it = 0; it < 4; it++) {
            int idx = tid + 256 * it;
            int r = idx >> 3, c8 = (idx & 7) * 8;
            size_t gk = base + 1024 + (size_t)(kt * 128 + r) * 3072 + c8;
            *(uint4*)&sm[OFF_KH + r * VS + c8] = *(const uint4*)&qh[gk];
            *(uint4*)&sm[OFF_KL + r * VS + c8] = *(const uint4*)&ql[gk];
            size_t gv = base + 2048 + (size_t)(kt * 128 + r) * 3072 + c8;
            *(uint4*)&sm[OFF_VH + r * VS + c8] = *(const uint4*)&qh[gv];
            *(uint4*)&sm[OFF_VL + r * VS + c8] = *(const uint4*)&ql[gv];
        }
        __syncthreads();

        float sAcc[16][4];
        #pragma unroll
        for (int j = 0; j < 16; j++)
            #pragma unroll
            for (int r = 0; r < 4; r++) sAcc[j][r] = 0.f;

        #pragma unroll
        for (int ks = 0; ks < 4; ks++) {
            #pragma unroll
            for (int p = 0; p < 8; p++) {
                uint32_t off = (uint32_t)((p * 16 + nr) * VS + ks * 16 + kc8) * 2;
                uint32_t kbH[4], kbL[4];
                LDSM_X4(kbH, sKh + off);
                LDSM_X4(kbL, sKl + off);
                MMA_BF16(sAcc[2 * p], qA[0][ks], &kbH[0]);
                MMA_BF16(sAcc[2 * p], qA[0][ks], &kbL[0]);
                MMA_BF16(sAcc[2 * p], qA[1][ks], &kbH[0]);
                MMA_BF16(sAcc[2 * p + 1], qA[0][ks], &kbH[2]);
                MMA_BF16(sAcc[2 * p + 1], qA[0][ks], &kbL[2]);
                MMA_BF16(sAcc[2 * p + 1], qA[1][ks], &kbH[2]);
            }
        }

        #pragma unroll
        for (int j = 0; j < 16; j++)
            #pragma unroll
            for (int r = 0; r < 4; r++) sAcc[j][r] *= 0.125f;

        if (kt == qt) {
            int r0 = wid * 16 + (lane >> 2);
            #pragma unroll
            for (int j = 0; j < 16; j++) {
                int c0 = j * 8 + (lane & 3) * 2;
                if (c0 > r0)     sAcc[j][0] = -1e30f;
                if (c0 + 1 > r0) sAcc[j][1] = -1e30f;
                if (c0 > r0 + 8)     sAcc[j][2] = -1e30f;
                if (c0 + 1 > r0 + 8) sAcc[j][3] = -1e30f;
            }
        }

        #pragma unroll
        for (int hf = 0; hf < 2; hf++) {
            float rm = -1e30f;
            #pragma unroll
            for (int j = 0; j < 16; j++)
                rm = fmaxf(rm, fmaxf(sAcc[j][2 * hf], sAcc[j][2 * hf + 1]));
            rm = fmaxf(rm, __shfl_xor_sync(0xffffffffu, rm, 1));
            rm = fmaxf(rm, __shfl_xor_sync(0xffffffffu, rm, 2));
            float nm = fmaxf(mS[hf], rm);
            float alpha = __expf(mS[hf] - nm);
            mS[hf] = nm;
            float sum = 0.f;
            #pragma unroll
            for (int j = 0; j < 16; j++) {
                float p0 = __expf(sAcc[j][2 * hf] - nm);
                float p1 = __expf(sAcc[j][2 * hf + 1] - nm);
                sAcc[j][2 * hf] = p0;
                sAcc[j][2 * hf + 1] = p1;
                sum += p0 + p1;
            }
            sum += __shfl_xor_sync(0xffffffffu, sum, 1);
            sum += __shfl_xor_sync(0xffffffffu, sum, 2);
            lS[hf] = lS[hf] * alpha + sum;
            #pragma unroll
            for (int j = 0; j < 8; j++) {
                oAcc[j][2 * hf] *= alpha;
                oAcc[j][2 * hf + 1] *= alpha;
            }
        }

        uint32_t pH[8][4], pL[8][4];
        #pragma unroll
        for (int t = 0; t < 8; t++) {
            #pragma unroll
            for (int q = 0; q < 4; q++) {
                int nt = 2 * t + (q >> 1);
                int i0 = (q & 1) * 2;
                __nv_bfloat16 h0, l0, h1, l1;
                split_bf16(sAcc[nt][i0], h0, l0);
                split_bf16(sAcc[nt][i0 + 1], h1, l1);
                pH[t][q] = pack2(h0, h1);
                pL[t][q] = pack2(l0, l1);
            }
        }

        // O += P @ V  — B-fragments via ldmatrix.trans on row-major V.
        #pragma unroll
        for (int t = 0; t < 8; t++) {
            #pragma unroll
            for (int p = 0; p < 4; p++) {
                uint32_t off = (uint32_t)((t * 16 + vr) * VS + p * 16 + vc) * 2;
                uint32_t vbH[4], vbL[4];
                LDSM_X4_T(vbH, sVh + off);
                LDSM_X4_T(vbL, sVl + off);
                MMA_BF16(oAcc[2 * p], pH[t], &vbH[0]);
                MMA_BF16(oAcc[2 * p], pH[t], &vbL[0]);
                MMA_BF16(oAcc[2 * p], pL[t], &vbH[0]);
                MMA_BF16(oAcc[2 * p + 1], pH[t], &vbH[2]);
                MMA_BF16(oAcc[2 * p + 1], pH[t], &vbL[2]);
                MMA_BF16(oAcc[2 * p + 1], pL[t], &vbH[2]);
            }
        }
    }

    {
        float inv0 = 1.0f / lS[0];
        float inv1 = 1.0f / lS[1];
        int r0 = q0 + wid * 16 + (lane >> 2);
        size_t row0 = (size_t)b * TT + r0;
        #pragma unroll
        for (int j = 0; j < 8; j++) {
            int col = h * 64 + j * 8 + (lane & 3) * 2;
            float y0 = oAcc[j][0] * inv0, y1 = oAcc[j][1] * inv0;
            float y2 = oAcc[j][2] * inv1, y3 = oAcc[j][3] * inv1;
            __nv_bfloat16 h0, l0, h1, l1, h2, l2, h3, l3;
            split_bf16(y0, h0, l0); split_bf16(y1, h1, l1);
            split_bf16(y2, h2, l2); split_bf16(y3, h3, l3);
            *(uint32_t*)&yh[row0 * 1024 + col] = pack2(h0, h1);
            *(uint32_t*)&yl[row0 * 1024 + col] = pack2(l0, l1);
            *(uint32_t*)&yh[(row0 + 8) * 1024 + col] = pack2(h2, h3);
            *(uint32_t*)&yl[(row0 + 8) * 1024 + col] = pack2(l2, l3);
        }
    }
}

// ---------------------------------------------------------------------------
extern "C" void kernel_launch(void* const* d_in, const int* in_sizes, int n_in,
                              void* d_out, int out_size)
{
    const float* x      = (const float*)d_in[0];
    const float* W_attn = (const float*)d_in[1];
    const float* b_attn = (const float*)d_in[2];
    const float* W_proj = (const float*)d_in[3];
    const float* b_proj = (const float*)d_in[4];
    float* out = (float*)d_out;

    __nv_bfloat16 *qkvh, *qkvl, *wah, *wal, *wph, *wpl, *yh, *yl;
    cudaGetSymbolAddress((void**)&qkvh, g_qkvh);
    cudaGetSymbolAddress((void**)&qkvl, g_qkvl);
    cudaGetSymbolAddress((void**)&wah, g_wah);
    cudaGetSymbolAddress((void**)&wal, g_wal);
    cudaGetSymbolAddress((void**)&wph, g_wph);
    cudaGetSymbolAddress((void**)&wpl, g_wpl);
    cudaGetSymbolAddress((void**)&yh, g_yh);
    cudaGetSymbolAddress((void**)&yl, g_yl);

    static bool attr_set = false;
    if (!attr_set) {
        cudaFuncSetAttribute(flash_attn_mma_kernel,
                             cudaFuncAttributeMaxDynamicSharedMemorySize,
                             ATTN_SMEM);
        attr_set = true;
    }

    // 1) weight transposes/splits
    {
        dim3 g(3 * DD / 32, EE / 32), b(32, 8);
        transpose_split_kernel<<<g, b>>>(W_attn, wah, wal, EE, 3 * DD);
    }
    {
        dim3 g(EE / 32, DD / 32), b(32, 8);
        transpose_split_kernel<<<g, b>>>(W_proj, wph, wpl, DD, EE);
    }

    // 2) QKV = x @ W_attn + b_attn -> bf16 hi/lo (x split fused into loader)
    {
        dim3 grid(3 * DD / 128, MM / 128);  // (24, 32)
        gemm_mma_kernel<<<grid, 256>>>(
            x, nullptr, nullptr, wah, wal, b_attn, nullptr, qkvh, qkvl,
            MM, 3 * DD, GK, 1);
    }

    // 3) flash attention -> yh/yl
    {
        dim3 grid(TT / 128, BB * HH);       // (16, 32)
        flash_attn_mma_kernel<<<grid, 256, ATTN_SMEM>>>(qkvh, qkvl, yh, yl);
    }

    // 4) out = y @ W_proj + b_proj  (fp32)
    {
        dim3 grid(EE / 128, MM / 128);      // (8, 32)
        gemm_mma_kernel<<<grid, 256>>>(
            nullptr, yh, yl, wph, wpl, b_proj, out, nullptr, nullptr,
            MM, EE, GK, 0);
    }
}

// round 17
// speedup vs baseline: 1.1206x; 1.1206x over previous
#include <cuda_runtime.h>
#include <cuda_bf16.h>
#include <cstdint>

// Problem constants
#define TT 2048
#define EE 1024
#define DD 1024
#define HH 16
#define HDIM 64
#define BB 2
#define MM (BB * TT)   // 4096
#define GK 1024        // K of both GEMMs

// ---------------------------------------------------------------------------
// Scratch
// ---------------------------------------------------------------------------
__device__ __nv_bfloat16 g_qkvh[(size_t)MM * 3 * DD];
__device__ __nv_bfloat16 g_qkvl[(size_t)MM * 3 * DD];
__device__ __nv_bfloat16 g_xh[(size_t)MM * EE];
__device__ __nv_bfloat16 g_xl[(size_t)MM * EE];
__device__ __nv_bfloat16 g_wah[(size_t)3 * DD * EE];
__device__ __nv_bfloat16 g_wal[(size_t)3 * DD * EE];
__device__ __nv_bfloat16 g_wph[(size_t)EE * DD];
__device__ __nv_bfloat16 g_wpl[(size_t)EE * DD];
__device__ __nv_bfloat16 g_yh[(size_t)MM * DD];
__device__ __nv_bfloat16 g_yl[(size_t)MM * DD];

// ---------------------------------------------------------------------------
// PTX helpers (base-target only)
// ---------------------------------------------------------------------------
__device__ __forceinline__ uint32_t smem_u32(const void* p) {
    uint32_t a;
    asm("{ .reg .u64 t; cvta.to.shared.u64 t, %1; cvt.u32.u64 %0, t; }"
        : "=r"(a) : "l"(p));
    return a;
}

#define LDSM_X4(R, addr) \
    asm volatile("ldmatrix.sync.aligned.m8n8.x4.shared.b16 {%0,%1,%2,%3}, [%4];" \
        : "=r"((R)[0]), "=r"((R)[1]), "=r"((R)[2]), "=r"((R)[3]) : "r"(addr))

#define LDSM_X4_T(R, addr) \
    asm volatile("ldmatrix.sync.aligned.m8n8.x4.trans.shared.b16 {%0,%1,%2,%3}, [%4];" \
        : "=r"((R)[0]), "=r"((R)[1]), "=r"((R)[2]), "=r"((R)[3]) : "r"(addr))

#define MMA_BF16(D, A, B) \
    asm volatile("mma.sync.aligned.m16n8k16.row.col.f32.bf16.bf16.f32 " \
        "{%0,%1,%2,%3},{%4,%5,%6,%7},{%8,%9},{%0,%1,%2,%3};" \
        : "+f"((D)[0]), "+f"((D)[1]), "+f"((D)[2]), "+f"((D)[3]) \
        : "r"((A)[0]), "r"((A)[1]), "r"((A)[2]), "r"((A)[3]), \
          "r"((B)[0]), "r"((B)[1]))

#define CP_ASYNC16(dst, src) \
    asm volatile("cp.async.cg.shared.global [%0], [%1], 16;" \
        :: "r"(dst), "l"(src) : "memory")
#define CP_COMMIT() asm volatile("cp.async.commit_group;" ::: "memory")
#define CP_WAIT1() asm volatile("cp.async.wait_group 1;" ::: "memory")
#define CP_WAIT0() asm volatile("cp.async.wait_group 0;" ::: "memory")

__device__ __forceinline__ void split_bf16(float v, __nv_bfloat16& h, __nv_bfloat16& l) {
    h = __float2bfloat16(v);
    l = __float2bfloat16(v - __bfloat162float(h));
}
__device__ __forceinline__ uint32_t pack2(__nv_bfloat16 a, __nv_bfloat16 b) {
    __nv_bfloat162 t(a, b);
    return *(uint32_t*)&t;
}

// ---------------------------------------------------------------------------
// Split/convert kernels
// ---------------------------------------------------------------------------
__global__ void split_kernel(const float* __restrict__ in,
                             __nv_bfloat16* __restrict__ hi,
                             __nv_bfloat16* __restrict__ lo, int n4)
{
    int i = blockIdx.x * blockDim.x + threadIdx.x;
    if (i >= n4) return;
    float4 v = ((const float4*)in)[i];
    __nv_bfloat16 h0, h1, h2, h3, l0, l1, l2, l3;
    split_bf16(v.x, h0, l0); split_bf16(v.y, h1, l1);
    split_bf16(v.z, h2, l2); split_bf16(v.w, h3, l3);
    ((__nv_bfloat162*)hi)[2*i]   = __nv_bfloat162(h0, h1);
    ((__nv_bfloat162*)hi)[2*i+1] = __nv_bfloat162(h2, h3);
    ((__nv_bfloat162*)lo)[2*i]   = __nv_bfloat162(l0, l1);
    ((__nv_bfloat162*)lo)[2*i+1] = __nv_bfloat162(l2, l3);
}

__global__ void transpose_split_kernel(const float* __restrict__ W,
                                       __nv_bfloat16* __restrict__ Th,
                                       __nv_bfloat16* __restrict__ Tl,
                                       int K, int N)
{
    __shared__ float tile[32][33];
    int kb = blockIdx.y * 32, nb = blockIdx.x * 32;
    int x = threadIdx.x, y0 = threadIdx.y;
    #pragma unroll
    for (int dy = 0; dy < 32; dy += 8)
        tile[y0 + dy][x] = W[(size_t)(kb + y0 + dy) * N + nb + x];
    __syncthreads();
    #pragma unroll
    for (int dy = 0; dy < 32; dy += 8) {
        float v = tile[x][y0 + dy];
        __nv_bfloat16 h, l;
        split_bf16(v, h, l);
        size_t o = (size_t)(nb + y0 + dy) * K + kb + x;
        Th[o] = h;
        Tl[o] = l;
    }
}

// ---------------------------------------------------------------------------
// mma.sync split-bf16 GEMM — exact R10 config (proven 283.8us on QKV).
// ---------------------------------------------------------------------------
#define GS 40

__global__ __launch_bounds__(256) void gemm_mma_kernel(
    const __nv_bfloat16* __restrict__ Ah, const __nv_bfloat16* __restrict__ Al,
    const __nv_bfloat16* __restrict__ Bh, const __nv_bfloat16* __restrict__ Bl,
    const float* __restrict__ bias, float* __restrict__ C,
    __nv_bfloat16* __restrict__ Ch, __nv_bfloat16* __restrict__ Cl,
    int M, int N, int K, int mode)
{
    __shared__ __nv_bfloat16 sA[2][128][GS];
    __shared__ __nv_bfloat16 sB[2][128][GS];

    const int tid = threadIdx.x;
    const int lane = tid & 31;
    const int wid = tid >> 5;
    const int wm = wid & 3;
    const int wn = wid >> 2;
    const int m0 = blockIdx.y * 128;
    const int n0 = blockIdx.x * 128;

    const int lrow = tid >> 1;
    const int lseg = (tid & 1) * 16;

    float acc[2][8][4];
    #pragma unroll
    for (int i = 0; i < 2; i++)
        #pragma unroll
        for (int j = 0; j < 8; j++)
            #pragma unroll
            for (int r = 0; r < 4; r++) acc[i][j][r] = 0.f;

    const uint32_t sA0 = smem_u32(&sA[0][0][0]);
    const uint32_t sA1 = smem_u32(&sA[1][0][0]);
    const uint32_t sB0 = smem_u32(&sB[0][0][0]);
    const uint32_t sB1 = smem_u32(&sB[1][0][0]);

    uint4 pre[8];
    {
        size_t ra = (size_t)(m0 + lrow) * K + lseg;
        size_t rb = (size_t)(n0 + lrow) * K + lseg;
        pre[0] = *(const uint4*)&Ah[ra];
        pre[1] = *(const uint4*)&Ah[ra + 8];
        pre[2] = *(const uint4*)&Al[ra];
        pre[3] = *(const uint4*)&Al[ra + 8];
        pre[4] = *(const uint4*)&Bh[rb];
        pre[5] = *(const uint4*)&Bh[rb + 8];
        pre[6] = *(const uint4*)&Bl[rb];
        pre[7] = *(const uint4*)&Bl[rb + 8];
    }

    const int NC = K >> 5;
    for (int ch = 0; ch < NC; ch++) {
        *(uint4*)&sA[0][lrow][lseg]     = pre[0];
        *(uint4*)&sA[0][lrow][lseg + 8] = pre[1];
        *(uint4*)&sA[1][lrow][lseg]     = pre[2];
        *(uint4*)&sA[1][lrow][lseg + 8] = pre[3];
        *(uint4*)&sB[0][lrow][lseg]     = pre[4];
        *(uint4*)&sB[0][lrow][lseg + 8] = pre[5];
        *(uint4*)&sB[1][lrow][lseg]     = pre[6];
        *(uint4*)&sB[1][lrow][lseg + 8] = pre[7];
        __syncthreads();

        if (ch + 1 < NC) {
            int k0 = (ch + 1) * 32;
            size_t ra = (size_t)(m0 + lrow) * K + k0 + lseg;
            size_t rb = (size_t)(n0 + lrow) * K + k0 + lseg;
            pre[0] = *(const uint4*)&Ah[ra];
            pre[1] = *(const uint4*)&Ah[ra + 8];
            pre[2] = *(const uint4*)&Al[ra];
            pre[3] = *(const uint4*)&Al[ra + 8];
            pre[4] = *(const uint4*)&Bh[rb];
            pre[5] = *(const uint4*)&Bh[rb + 8];
            pre[6] = *(const uint4*)&Bl[rb];
            pre[7] = *(const uint4*)&Bl[rb + 8];
        }

        #pragma unroll
        for (int ks = 0; ks < 2; ks++) {
            uint32_t aA[2][2][4];
            {
                int r = lane & 15, kh = lane >> 4;
                #pragma unroll
                for (int mt = 0; mt < 2; mt++) {
                    uint32_t off =
                        (uint32_t)((wm * 32 + mt * 16 + r) * GS + ks * 16 + kh * 8) * 2;
                    LDSM_X4(aA[0][mt], sA0 + off);
                    LDSM_X4(aA[1][mt], sA1 + off);
                }
            }
            uint32_t bB[2][8][2];
            {
                int nr = ((lane >> 4) << 3) + (lane & 7);
                int kc = ks * 16 + (((lane >> 3) & 1) << 3);
                #pragma unroll
                for (int p = 0; p < 4; p++) {
                    uint32_t off =
                        (uint32_t)((wn * 64 + p * 16 + nr) * GS + kc) * 2;
                    uint32_t t[4];
                    LDSM_X4(t, sB0 + off);
                    bB[0][2 * p][0] = t[0]; bB[0][2 * p][1] = t[1];
                    bB[0][2 * p + 1][0] = t[2]; bB[0][2 * p + 1][1] = t[3];
                    LDSM_X4(t, sB1 + off);
                    bB[1][2 * p][0] = t[0]; bB[1][2 * p][1] = t[1];
                    bB[1][2 * p + 1][0] = t[2]; bB[1][2 * p + 1][1] = t[3];
                }
            }
            #pragma unroll
            for (int mt = 0; mt < 2; mt++)
                #pragma unroll
                for (int nt = 0; nt < 8; nt++) {
                    MMA_BF16(acc[mt][nt], aA[0][mt], bB[0][nt]);
                    MMA_BF16(acc[mt][nt], aA[0][mt], bB[1][nt]);
                    MMA_BF16(acc[mt][nt], aA[1][mt], bB[0][nt]);
                }
        }
        __syncthreads();
    }

    // Epilogue
    #pragma unroll
    for (int mt = 0; mt < 2; mt++) {
        int m = m0 + wm * 32 + mt * 16 + (lane >> 2);
        #pragma unroll
        for (int nt = 0; nt < 8; nt++) {
            int n = n0 + wn * 64 + nt * 8 + ((lane & 3) << 1);
            float b0 = bias[n], b1 = bias[n + 1];
            float v0 = acc[mt][nt][0] + b0, v1 = acc[mt][nt][1] + b1;
            float v2 = acc[mt][nt][2] + b0, v3 = acc[mt][nt][3] + b1;
            if (mode == 0) {
                *(float2*)&C[(size_t)m * N + n] = make_float2(v0, v1);
                *(float2*)&C[(size_t)(m + 8) * N + n] = make_float2(v2, v3);
            } else {
                __nv_bfloat16 h0, l0, h1, l1, h2, l2, h3, l3;
                split_bf16(v0, h0, l0); split_bf16(v1, h1, l1);
                split_bf16(v2, h2, l2); split_bf16(v3, h3, l3);
                *(uint32_t*)&Ch[(size_t)m * N + n] = pack2(h0, h1);
                *(uint32_t*)&Cl[(size_t)m * N + n] = pack2(l0, l1);
                *(uint32_t*)&Ch[(size_t)(m + 8) * N + n] = pack2(h2, h3);
                *(uint32_t*)&Cl[(size_t)(m + 8) * N + n] = pack2(l2, l3);
            }
        }
    }
}

// ---------------------------------------------------------------------------
// Tensor-core flash attention with cp.async double-buffered K/V.
// 2 stages x 4 tiles (KH,KL,VH,VL) = 147.5KB smem, 1 CTA/SM.
// Loads for tile kt+1 fly behind tile kt's MMA/softmax. V row-major +
// ldmatrix.trans. Q prologue borrows stage 1 (overwritten from kt=1 on,
// after Q fragments are register-resident).
// ---------------------------------------------------------------------------
#define VS 72
#define TILE_B (128 * VS * 2)          // 18432 bytes per tile
#define STAGE_B (4 * TILE_B)           // 73728 bytes per stage
#define ATTN_SMEM (2 * STAGE_B)        // 147456 bytes

__global__ __launch_bounds__(256) void flash_attn_mma_kernel(
    const __nv_bfloat16* __restrict__ qh, const __nv_bfloat16* __restrict__ ql,
    __nv_bfloat16* __restrict__ yh, __nv_bfloat16* __restrict__ yl)
{
    extern __shared__ __nv_bfloat16 sm[];
    const uint32_t sbase = smem_u32(sm);

    const int qt = 15 - blockIdx.x;
    const int bh = blockIdx.y;
    const int b = bh >> 4, h = bh & 15;
    const int tid = threadIdx.x;
    const int lane = tid & 31;
    const int wid = tid >> 5;
    const int q0 = qt * 128;
    const size_t base = ((size_t)b * TT) * 3072 + (size_t)h * 64;

    // per-thread loader coordinates (16 x 16B chunks per tile-group)
    // it in 0..3: idx = tid + 256*it; r = idx>>3; c8 = (idx&7)*8
    // K source: base+1024, V source: base+2048; dst offset (r*VS + c8)*2

    // Prologue: load Q into stage 1 tiles 0/1 (direct stores), extract frags.
    #pragma unroll
    for (int it = 0; it < 4; it++) {
        int idx = tid + 256 * it;
        int r = idx >> 3, c8 = (idx & 7) * 8;
        size_t g = base + (size_t)(q0 + r) * 3072 + c8;
        uint32_t d = (uint32_t)(r * VS + c8) * 2;
        *(uint4*)((char*)sm + STAGE_B + d)          = *(const uint4*)&qh[g];
        *(uint4*)((char*)sm + STAGE_B + TILE_B + d) = *(const uint4*)&ql[g];
    }
    __syncthreads();

    uint32_t qA[2][4][4];
    {
        int r = lane & 15, kh = lane >> 4;
        #pragma unroll
        for (int ks = 0; ks < 4; ks++) {
            uint32_t off = (uint32_t)((wid * 16 + r) * VS + ks * 16 + kh * 8) * 2;
            LDSM_X4(qA[0][ks], sbase + STAGE_B + off);
            LDSM_X4(qA[1][ks], sbase + STAGE_B + TILE_B + off);
        }
    }

    // Issue kt=0 loads into stage 0 (no barrier needed: stage 0 untouched).
    {
        #pragma unroll
        for (int it = 0; it < 4; it++) {
            int idx = tid + 256 * it;
            int r = idx >> 3, c8 = (idx & 7) * 8;
            uint32_t d = sbase + (uint32_t)(r * VS + c8) * 2;
            size_t gk = base + 1024 + (size_t)(r) * 3072 + c8;   // kt=0
            size_t gv = base + 2048 + (size_t)(r) * 3072 + c8;
            CP_ASYNC16(d,              &qh[gk]);
            CP_ASYNC16(d + TILE_B,     &ql[gk]);
            CP_ASYNC16(d + 2 * TILE_B, &qh[gv]);
            CP_ASYNC16(d + 3 * TILE_B, &ql[gv]);
        }
        CP_COMMIT();
    }

    float mS[2] = {-1e30f, -1e30f};
    float lS[2] = {0.f, 0.f};
    float oAcc[8][4];
    #pragma unroll
    for (int j = 0; j < 8; j++)
        #pragma unroll
        for (int r = 0; r < 4; r++) oAcc[j][r] = 0.f;

    const int nr = ((lane >> 4) << 3) + (lane & 7);
    const int kc8 = ((lane >> 3) & 1) << 3;
    const int vr = lane & 15;
    const int vc = (lane >> 4) << 3;

    for (int kt = 0; kt <= qt; kt++) {
        // All reads of stage (kt+1)&1 (from iteration kt-1, or Q prologue)
        // are done before we overwrite it with kt+1's loads.
        __syncthreads();
        if (kt + 1 <= qt) {
            uint32_t st = sbase + (uint32_t)((kt + 1) & 1) * STAGE_B;
            #pragma unroll
            for (int it = 0; it < 4; it++) {
                int idx = tid + 256 * it;
                int r = idx >> 3, c8 = (idx & 7) * 8;
                uint32_t d = st + (uint32_t)(r * VS + c8) * 2;
                size_t gk = base + 1024 + (size_t)((kt + 1) * 128 + r) * 3072 + c8;
                size_t gv = base + 2048 + (size_t)((kt + 1) * 128 + r) * 3072 + c8;
                CP_ASYNC16(d,              &qh[gk]);
                CP_ASYNC16(d + TILE_B,     &ql[gk]);
                CP_ASYNC16(d + 2 * TILE_B, &qh[gv]);
                CP_ASYNC16(d + 3 * TILE_B, &ql[gv]);
            }
            CP_COMMIT();
            CP_WAIT1();   // kt's group complete; kt+1's stays in flight
        } else {
            CP_WAIT0();   // final tile: drain everything
        }
        __syncthreads();  // completed cp.async data visible to all threads

        const uint32_t sKH = sbase + (uint32_t)(kt & 1) * STAGE_B;
        const uint32_t sKL = sKH + TILE_B;
        const uint32_t sVH = sKH + 2 * TILE_B;
        const uint32_t sVL = sKH + 3 * TILE_B;

        float sAcc[16][4];
        #pragma unroll
        for (int j = 0; j < 16; j++)
            #pragma unroll
            for (int r = 0; r < 4; r++) sAcc[j][r] = 0.f;

        #pragma unroll
        for (int ks = 0; ks < 4; ks++) {
            #pragma unroll
            for (int p = 0; p < 8; p++) {
                uint32_t off = (uint32_t)((p * 16 + nr) * VS + ks * 16 + kc8) * 2;
                uint32_t kbH[4], kbL[4];
                LDSM_X4(kbH, sKH + off);
                LDSM_X4(kbL, sKL + off);
                MMA_BF16(sAcc[2 * p], qA[0][ks], &kbH[0]);
                MMA_BF16(sAcc[2 * p], qA[0][ks], &kbL[0]);
                MMA_BF16(sAcc[2 * p], qA[1][ks], &kbH[0]);
                MMA_BF16(sAcc[2 * p + 1], qA[0][ks], &kbH[2]);
                MMA_BF16(sAcc[2 * p + 1], qA[0][ks], &kbL[2]);
                MMA_BF16(sAcc[2 * p + 1], qA[1][ks], &kbH[2]);
            }
        }

        #pragma unroll
        for (int j = 0; j < 16; j++)
            #pragma unroll
            for (int r = 0; r < 4; r++) sAcc[j][r] *= 0.125f;

        if (kt == qt) {
            int r0 = wid * 16 + (lane >> 2);
            #pragma unroll
            for (int j = 0; j < 16; j++) {
                int c0 = j * 8 + (lane & 3) * 2;
                if (c0 > r0)     sAcc[j][0] = -1e30f;
                if (c0 + 1 > r0) sAcc[j][1] = -1e30f;
                if (c0 > r0 + 8)     sAcc[j][2] = -1e30f;
                if (c0 + 1 > r0 + 8) sAcc[j][3] = -1e30f;
            }
        }

        #pragma unroll
        for (int hf = 0; hf < 2; hf++) {
            float rm = -1e30f;
            #pragma unroll
            for (int j = 0; j < 16; j++)
                rm = fmaxf(rm, fmaxf(sAcc[j][2 * hf], sAcc[j][2 * hf + 1]));
            rm = fmaxf(rm, __shfl_xor_sync(0xffffffffu, rm, 1));
            rm = fmaxf(rm, __shfl_xor_sync(0xffffffffu, rm, 2));
            float nm = fmaxf(mS[hf], rm);
            float alpha = __expf(mS[hf] - nm);
            mS[hf] = nm;
            float sum = 0.f;
            #pragma unroll
            for (int j = 0; j < 16; j++) {
                float p0 = __expf(sAcc[j][2 * hf] - nm);
                float p1 = __expf(sAcc[j][2 * hf + 1] - nm);
                sAcc[j][2 * hf] = p0;
                sAcc[j][2 * hf + 1] = p1;
                sum += p0 + p1;
            }
            sum += __shfl_xor_sync(0xffffffffu, sum, 1);
            sum += __shfl_xor_sync(0xffffffffu, sum, 2);
            lS[hf] = lS[hf] * alpha + sum;
            #pragma unroll
            for (int j = 0; j < 8; j++) {
                oAcc[j][2 * hf] *= alpha;
                oAcc[j][2 * hf + 1] *= alpha;
            }
        }

        uint32_t pH[8][4], pL[8][4];
        #pragma unroll
        for (int t = 0; t < 8; t++) {
            #pragma unroll
            for (int q = 0; q < 4; q++) {
                int nt = 2 * t + (q >> 1);
                int i0 = (q & 1) * 2;
                __nv_bfloat16 h0, l0, h1, l1;
                split_bf16(sAcc[nt][i0], h0, l0);
                split_bf16(sAcc[nt][i0 + 1], h1, l1);
                pH[t][q] = pack2(h0, h1);
                pL[t][q] = pack2(l0, l1);
            }
        }

        // O += P @ V  — ldmatrix.trans on row-major V.
        #pragma unroll
        for (int t = 0; t < 8; t++) {
            #pragma unroll
            for (int p = 0; p < 4; p++) {
                uint32_t off = (uint32_t)((t * 16 + vr) * VS + p * 16 + vc) * 2;
                uint32_t vbH[4], vbL[4];
                LDSM_X4_T(vbH, sVH + off);
                LDSM_X4_T(vbL, sVL + off);
                MMA_BF16(oAcc[2 * p], pH[t], &vbH[0]);
                MMA_BF16(oAcc[2 * p], pH[t], &vbL[0]);
                MMA_BF16(oAcc[2 * p], pL[t], &vbH[0]);
                MMA_BF16(oAcc[2 * p + 1], pH[t], &vbH[2]);
                MMA_BF16(oAcc[2 * p + 1], pH[t], &vbL[2]);
                MMA_BF16(oAcc[2 * p + 1], pL[t], &vbH[2]);
            }
        }
    }

    {
        float inv0 = 1.0f / lS[0];
        float inv1 = 1.0f / lS[1];
        int r0 = q0 + wid * 16 + (lane >> 2);
        size_t row0 = (size_t)b * TT + r0;
        #pragma unroll
        for (int j = 0; j < 8; j++) {
            int col = h * 64 + j * 8 + (lane & 3) * 2;
            float y0 = oAcc[j][0] * inv0, y1 = oAcc[j][1] * inv0;
            float y2 = oAcc[j][2] * inv1, y3 = oAcc[j][3] * inv1;
            __nv_bfloat16 h0, l0, h1, l1, h2, l2, h3, l3;
            split_bf16(y0, h0, l0); split_bf16(y1, h1, l1);
            split_bf16(y2, h2, l2); split_bf16(y3, h3, l3);
            *(uint32_t*)&yh[row0 * 1024 + col] = pack2(h0, h1);
            *(uint32_t*)&yl[row0 * 1024 + col] = pack2(l0, l1);
            *(uint32_t*)&yh[(row0 + 8) * 1024 + col] = pack2(h2, h3);
            *(uint32_t*)&yl[(row0 + 8) * 1024 + col] = pack2(l2, l3);
        }
    }
}

// ---------------------------------------------------------------------------
extern "C" void kernel_launch(void* const* d_in, const int* in_sizes, int n_in,
                              void* d_out, int out_size)
{
    const float* x      = (const float*)d_in[0];
    const float* W_attn = (const float*)d_in[1];
    const float* b_attn = (const float*)d_in[2];
    const float* W_proj = (const float*)d_in[3];
    const float* b_proj = (const float*)d_in[4];
    float* out = (float*)d_out;

    __nv_bfloat16 *qkvh, *qkvl, *xh, *xl, *wah, *wal, *wph, *wpl, *yh, *yl;
    cudaGetSymbolAddress((void**)&qkvh, g_qkvh);
    cudaGetSymbolAddress((void**)&qkvl, g_qkvl);
    cudaGetSymbolAddress((void**)&xh, g_xh);
    cudaGetSymbolAddress((void**)&xl, g_xl);
    cudaGetSymbolAddress((void**)&wah, g_wah);
    cudaGetSymbolAddress((void**)&wal, g_wal);
    cudaGetSymbolAddress((void**)&wph, g_wph);
    cudaGetSymbolAddress((void**)&wpl, g_wpl);
    cudaGetSymbolAddress((void**)&yh, g_yh);
    cudaGetSymbolAddress((void**)&yl, g_yl);

    static bool attr_set = false;
    if (!attr_set) {
        cudaFuncSetAttribute(flash_attn_mma_kernel,
                             cudaFuncAttributeMaxDynamicSharedMemorySize,
                             ATTN_SMEM);
        attr_set = true;
    }

    // 1) splits / transposes
    split_kernel<<<(MM * EE / 4 + 255) / 256, 256>>>(x, xh, xl, MM * EE / 4);
    {
        dim3 g(3 * DD / 32, EE / 32), b(32, 8);
        transpose_split_kernel<<<g, b>>>(W_attn, wah, wal, EE, 3 * DD);
    }
    {
        dim3 g(EE / 32, DD / 32), b(32, 8);
        transpose_split_kernel<<<g, b>>>(W_proj, wph, wpl, DD, EE);
    }

    // 2) QKV = x @ W_attn + b_attn -> bf16 hi/lo splits
    {
        dim3 grid(3 * DD / 128, MM / 128);  // (24, 32)
        gemm_mma_kernel<<<grid, 256>>>(
            xh, xl, wah, wal, b_attn, nullptr, qkvh, qkvl, MM, 3 * DD, GK, 1);
    }

    // 3) flash attention (cp.async double-buffered K/V) -> yh/yl
    {
        dim3 grid(TT / 128, BB * HH);       // (16, 32)
        flash_attn_mma_kernel<<<grid, 256, ATTN_SMEM>>>(qkvh, qkvl, yh, yl);
    }

    // 4) out = y @ W_proj + b_proj  (fp32)
    {
        dim3 grid(EE / 128, MM / 128);      // (8, 32)
        gemm_mma_kernel<<<grid, 256>>>(
            yh, yl, wph, wpl, b_proj, out, nullptr, nullptr, MM, EE, GK, 0);
    }
}